// round 15
// baseline (speedup 1.0000x reference)
#include <cuda_runtime.h>
#include <cuda_bf16.h>
#include <cuda_fp16.h>
#include <cstdint>
#include <cstddef>

#define NN 100000
#define NE 1600000
#define NH 4
#define DI 128
#define DO 32

#define SCB 512
#define NSB ((NN + SCB - 1) / SCB)    // 196 scan blocks

#define GT 128                         // gemm tile: nodes per CTA
#define NTILE ((NN + GT - 1) / GT)     // 782 CTAs

#define BPAD 68                        // smem word-stride for W tiles (conflict-free)
#define SMEMB (2 * 128 * BPAD * 4)     // hi + lo planes, bytes

// -------- scratch (no allocs allowed) --------
__device__ __half g_Hw[(size_t)NH * NN * DO];  // [h][n][o]  fp16, 25.6 MB
__device__ float g_ssrc[NN * NH];              // [n][h]
__device__ float g_stgt[NN * NH];
__device__ int   g_cnt[NN];
__device__ int   g_fill[NN];
__device__ int   g_rowptr[NN + 1];
__device__ int   g_esrc[NE];
__device__ int   g_bsum[NSB];
__device__ int   g_boff[NSB];

__device__ __forceinline__ int clampN(int v) {
    v = v < 0 ? 0 : v;
    return v >= NN ? NN - 1 : v;
}

// -------- kernel 0 --------
__global__ void k_init() {
    int i = blockIdx.x * blockDim.x + threadIdx.x;
    if (i < NN) { g_cnt[i] = 0; g_fill[i] = 0; }
    if (i == 0) g_rowptr[NN] = NE;
}

// ===== mma.sync bf16 helpers (baseline sm_80+ ISA) =====
__device__ __forceinline__ void bf16_split(float x, float y, uint32_t& hi, uint32_t& lo) {
    __nv_bfloat162 h = __floats2bfloat162_rn(x, y);
    float hx = __bfloat162float(h.x), hy = __bfloat162float(h.y);
    __nv_bfloat162 l = __floats2bfloat162_rn(x - hx, y - hy);
    hi = *(uint32_t*)&h;
    lo = *(uint32_t*)&l;
}
__device__ __forceinline__ void mma16816(float* c, const uint32_t* a, const uint32_t* b) {
    asm volatile(
        "mma.sync.aligned.m16n8k16.row.col.f32.bf16.bf16.f32 "
        "{%0,%1,%2,%3}, {%4,%5,%6,%7}, {%8,%9}, {%0,%1,%2,%3};"
        : "+f"(c[0]), "+f"(c[1]), "+f"(c[2]), "+f"(c[3])
        : "r"(a[0]), "r"(a[1]), "r"(a[2]), "r"(a[3]), "r"(b[0]), "r"(b[1]));
}

// -------- kernel A: bf16x2-split tensor-core GEMM + fused s_src/s_tgt --------
// CTA: 128 nodes x 128 outputs, K=128. W staged in smem pre-split (hi/lo).
__global__ __launch_bounds__(256) void k_gemm(const float* __restrict__ Hin,
                                              const float* __restrict__ W,
                                              const float* __restrict__ Asrc,
                                              const float* __restrict__ Atgt) {
    extern __shared__ uint32_t sb[];
    uint32_t* sBh = sb;                    // [128][BPAD] bf16x2 pairs (k,k+1)
    uint32_t* sBl = sb + 128 * BPAD;

    const int t = threadIdx.x;
    const int wid = t >> 5, lane = t & 31;
    const int warp_m = wid & 3, warp_n = wid >> 2;
    const int qr = lane >> 2, qc = lane & 3;
    const int nb = blockIdx.x * GT + warp_m * 32;

    // ---- stage + split W once per CTA: thread t -> row t>>1, half (t&1) ----
    {
        const int j  = t >> 1;
        const int kh = (t & 1) * 64;
        const float4* wrow = (const float4*)(W + (size_t)j * DI + kh);
        uint32_t* dh = sBh + j * BPAD + (kh >> 1);
        uint32_t* dl = sBl + j * BPAD + (kh >> 1);
#pragma unroll
        for (int q = 0; q < 16; q++) {
            float4 v = wrow[q];
            bf16_split(v.x, v.y, dh[q * 2],     dl[q * 2]);
            bf16_split(v.z, v.w, dh[q * 2 + 1], dl[q * 2 + 1]);
        }
    }
    __syncthreads();

    float C[2][8][4];
#pragma unroll
    for (int mt = 0; mt < 2; mt++)
#pragma unroll
        for (int nt = 0; nt < 8; nt++)
#pragma unroll
            for (int q = 0; q < 4; q++) C[mt][nt][q] = 0.f;

#pragma unroll
    for (int kk = 0; kk < 8; kk++) {
        const int k0 = kk * 16 + qc * 2;

        // A fragments (2 m-tiles), hi/lo split, direct from global (read once)
        uint32_t Ah[2][4], Al[2][4];
#pragma unroll
        for (int mt = 0; mt < 2; mt++) {
            int r0 = nb + mt * 16 + qr;
            int r1 = r0 + 8;
            r0 = r0 < NN ? r0 : NN - 1;
            r1 = r1 < NN ? r1 : NN - 1;
            const float* p0 = Hin + (size_t)r0 * DI + k0;
            const float* p1 = Hin + (size_t)r1 * DI + k0;
            float2 v;
            v = *(const float2*)p0;       bf16_split(v.x, v.y, Ah[mt][0], Al[mt][0]);
            v = *(const float2*)p1;       bf16_split(v.x, v.y, Ah[mt][1], Al[mt][1]);
            v = *(const float2*)(p0 + 8); bf16_split(v.x, v.y, Ah[mt][2], Al[mt][2]);
            v = *(const float2*)(p1 + 8); bf16_split(v.x, v.y, Ah[mt][3], Al[mt][3]);
        }

#pragma unroll
        for (int nt = 0; nt < 8; nt++) {
            const int jb = (warp_n * 64 + nt * 8 + qr) * BPAD + kk * 8;
            uint32_t Bh[2], Bl[2];
            Bh[0] = sBh[jb + qc];
            Bh[1] = sBh[jb + 4 + qc];
            Bl[0] = sBl[jb + qc];
            Bl[1] = sBl[jb + 4 + qc];
#pragma unroll
            for (int mt = 0; mt < 2; mt++) {
                mma16816(C[mt][nt], Ah[mt], Bh);
                mma16816(C[mt][nt], Ah[mt], Bl);
                mma16816(C[mt][nt], Al[mt], Bh);
            }
        }
    }

    // ---- epilogue: fp16 H_w stores + fused attention-logit dots ----
    const int h0 = warp_n * 2;
    float a0v[8], a1v[8], b0v[8], b1v[8];
#pragma unroll
    for (int nt = 0; nt < 8; nt++) {
        const int j = warp_n * 64 + nt * 8 + qc * 2;
        a0v[nt] = __ldg(&Asrc[j]); a1v[nt] = __ldg(&Asrc[j + 1]);
        b0v[nt] = __ldg(&Atgt[j]); b1v[nt] = __ldg(&Atgt[j + 1]);
    }

#pragma unroll
    for (int mt = 0; mt < 2; mt++) {
#pragma unroll
        for (int rh = 0; rh < 2; rh++) {
            const int node = nb + mt * 16 + qr + rh * 8;
            float ps0 = 0.f, ps1 = 0.f, pt0 = 0.f, pt1 = 0.f;
#pragma unroll
            for (int nt = 0; nt < 8; nt++) {
                const float c0 = C[mt][nt][rh * 2], c1 = C[mt][nt][rh * 2 + 1];
                if (nt < 4) { ps0 += c0 * a0v[nt] + c1 * a1v[nt]; pt0 += c0 * b0v[nt] + c1 * b1v[nt]; }
                else        { ps1 += c0 * a0v[nt] + c1 * a1v[nt]; pt1 += c0 * b0v[nt] + c1 * b1v[nt]; }
                if (node < NN) {
                    const int h = h0 + (nt >> 2);
                    const int o = (nt & 3) * 8 + qc * 2;
                    *(__half2*)&g_Hw[((size_t)h * NN + node) * DO + o] = __floats2half2_rn(c0, c1);
                }
            }
#pragma unroll
            for (int d = 1; d < 4; d <<= 1) {
                ps0 += __shfl_xor_sync(0xffffffffu, ps0, d);
                ps1 += __shfl_xor_sync(0xffffffffu, ps1, d);
                pt0 += __shfl_xor_sync(0xffffffffu, pt0, d);
                pt1 += __shfl_xor_sync(0xffffffffu, pt1, d);
            }
            if (qc == 0 && node < NN) {
                g_ssrc[node * NH + h0]     = ps0;
                g_ssrc[node * NH + h0 + 1] = ps1;
                g_stgt[node * NH + h0]     = pt0;
                g_stgt[node * NH + h0 + 1] = pt1;
            }
        }
    }
}

// -------- CSR build --------
__global__ __launch_bounds__(256) void k_hist(const int* __restrict__ ei) {
    int e = blockIdx.x * blockDim.x + threadIdx.x;
    if (e >= NE) return;
    atomicAdd(&g_cnt[clampN(ei[NE + e])], 1);
}

__global__ __launch_bounds__(256) void k_scan1() {
    int t = threadIdx.x;
    int i0 = blockIdx.x * SCB + t * 2;
    int v0 = (i0     < NN) ? g_cnt[i0]     : 0;
    int v1 = (i0 + 1 < NN) ? g_cnt[i0 + 1] : 0;
    int s = v0 + v1;
#pragma unroll
    for (int off = 16; off > 0; off >>= 1) s += __shfl_xor_sync(0xffffffffu, s, off);
    __shared__ int ws[8];
    if ((t & 31) == 0) ws[t >> 5] = s;
    __syncthreads();
    if (t == 0) {
        int tot = 0;
#pragma unroll
        for (int w = 0; w < 8; w++) tot += ws[w];
        g_bsum[blockIdx.x] = tot;
    }
}

__global__ __launch_bounds__(256) void k_scan2() {
    int t = threadIdx.x;
    int v = (t < NSB) ? g_bsum[t] : 0;
    int x = v;
    int lane = t & 31, warp = t >> 5;
#pragma unroll
    for (int off = 1; off < 32; off <<= 1) {
        int y = __shfl_up_sync(0xffffffffu, x, off);
        if (lane >= off) x += y;
    }
    __shared__ int ws[8];
    if (lane == 31) ws[warp] = x;
    __syncthreads();
    if (warp == 0) {
        int w = (lane < 8) ? ws[lane] : 0;
#pragma unroll
        for (int off = 1; off < 8; off <<= 1) {
            int y = __shfl_up_sync(0xffffffffu, w, off);
            if (lane >= off) w += y;
        }
        if (lane < 8) ws[lane] = w;
    }
    __syncthreads();
    int base = (warp > 0) ? ws[warp - 1] : 0;
    if (t < NSB) g_boff[t] = base + x - v;
}

__global__ __launch_bounds__(256) void k_scan3() {
    int t = threadIdx.x;
    int i0 = blockIdx.x * SCB + t * 2;
    int v0 = (i0     < NN) ? g_cnt[i0]     : 0;
    int v1 = (i0 + 1 < NN) ? g_cnt[i0 + 1] : 0;
    int tsum = v0 + v1;

    int x = tsum;
    int lane = t & 31, warp = t >> 5;
#pragma unroll
    for (int off = 1; off < 32; off <<= 1) {
        int y = __shfl_up_sync(0xffffffffu, x, off);
        if (lane >= off) x += y;
    }
    __shared__ int ws[8];
    if (lane == 31) ws[warp] = x;
    __syncthreads();
    if (warp == 0) {
        int w = (lane < 8) ? ws[lane] : 0;
#pragma unroll
        for (int off = 1; off < 8; off <<= 1) {
            int y = __shfl_up_sync(0xffffffffu, w, off);
            if (lane >= off) w += y;
        }
        if (lane < 8) ws[lane] = w;
    }
    __syncthreads();
    int wbase = (warp > 0) ? ws[warp - 1] : 0;
    int excl = g_boff[blockIdx.x] + wbase + x - tsum;

    if (i0     < NN) g_rowptr[i0]     = excl;
    if (i0 + 1 < NN) g_rowptr[i0 + 1] = excl + v0;
}

__global__ __launch_bounds__(256) void k_scatter(const int* __restrict__ ei) {
    int e = blockIdx.x * blockDim.x + threadIdx.x;
    if (e >= NE) return;
    int src = clampN(ei[e]);
    int tgt = clampN(ei[NE + e]);
    int pos = g_rowptr[tgt] + atomicAdd(&g_fill[tgt], 1);
    g_esrc[pos] = src;
}

// -------- kernel D: gather aggregation, one warp per target node --------
// lane -> (head = lane>>3, out quad o = (lane&7)*4); fp16 H_w gather (8B/lane).
__global__ __launch_bounds__(256) void k_agg(float* __restrict__ out) {
    int tgt = (blockIdx.x * blockDim.x + threadIdx.x) >> 5;
    if (tgt >= NN) return;
    int lane = threadIdx.x & 31;
    int h = lane >> 3;
    int o = (lane & 7) * 4;

    int beg = g_rowptr[tgt];
    int end = g_rowptr[tgt + 1];

    float4* dst = (float4*)&out[((size_t)h * NN + tgt) * DO + o];

    if (beg == end) {
        *dst = make_float4(0.f, 0.f, 0.f, 0.f);
        return;
    }

    float st = g_stgt[tgt * NH + h];
    float4 acc = make_float4(0.f, 0.f, 0.f, 0.f);
    float sum = 0.f;

    for (int i = beg; i < end; i++) {
        int src = g_esrc[i];
        float ss = g_ssrc[src * NH + h];
        float E  = ss + st;
        E = E > 0.f ? E : 0.2f * E;
        float x = __expf(E);
        sum += x;
        const uint2 raw = *(const uint2*)&g_Hw[((size_t)h * NN + src) * DO + o];
        const float2 f01 = __half22float2(*(const __half2*)&raw.x);
        const float2 f23 = __half22float2(*(const __half2*)&raw.y);
        acc.x += x * f01.x;
        acc.y += x * f01.y;
        acc.z += x * f23.x;
        acc.w += x * f23.y;
    }

    float inv = 1.0f / sum;
    float4 r;
    r.x = acc.x * inv; r.y = acc.y * inv; r.z = acc.z * inv; r.w = acc.w * inv;
    r.x = r.x > 0.f ? r.x : expm1f(r.x);
    r.y = r.y > 0.f ? r.y : expm1f(r.y);
    r.z = r.z > 0.f ? r.z : expm1f(r.z);
    r.w = r.w > 0.f ? r.w : expm1f(r.w);
    *dst = r;
}

extern "C" void kernel_launch(void* const* d_in, const int* in_sizes, int n_in,
                              void* d_out, int out_size) {
    const float* Hin  = (const float*)d_in[0];
    const int*   ei   = (const int*)d_in[1];
    const float* W    = (const float*)d_in[2];
    const float* Asrc = (const float*)d_in[3];
    const float* Atgt = (const float*)d_in[4];
    float* out = (float*)d_out;

    (void)in_sizes; (void)n_in; (void)out_size;

    cudaFuncSetAttribute(k_gemm, cudaFuncAttributeMaxDynamicSharedMemorySize, SMEMB);

    // launch order chosen so k_gemm is profile index 3
    k_init<<<(NN + 255) / 256, 256>>>();
    k_hist<<<(NE + 255) / 256, 256>>>(ei);
    k_scan1<<<NSB, 256>>>();
    k_gemm<<<NTILE, 256, SMEMB>>>(Hin, W, Asrc, Atgt);
    k_scan2<<<1, 256>>>();
    k_scan3<<<NSB, 256>>>();
    k_scatter<<<(NE + 255) / 256, 256>>>(ei);
    k_agg<<<(NN + 7) / 8, 256>>>(out);
}